// round 16
// baseline (speedup 1.0000x reference)
#include <cuda_runtime.h>
#include <cstdint>

// NerfRender integrate v13: v12 + sigma prefetched via cp.async alongside c
// (post-sort sigma = smem hit, no exposed DRAM latency). One warp per ray.
// R = 65536, N = 192 (t has 193). Output: rgb [R,3] then wi [R,192].

#define NP1 193
#define NS  192
#define VR  8
#define WPB 8
#define SH_S 576              // u32 offset of sigma region (after c)
#define SH_PER_WARP 768       // 576 (c) + 192 (sigma)
#define FULL 0xffffffffu
#define PAD_BITS 0x7149f2cau  // 1e30f: sorts above all real t, finite math

typedef uint32_t u32;

__device__ __forceinline__ void cp_async16(u32 saddr, const void* gptr) {
    asm volatile("cp.async.cg.shared.global [%0], [%1], 16;\n" :: "r"(saddr), "l"(gptr));
}
__device__ __forceinline__ void cp_async_commit() {
    asm volatile("cp.async.commit_group;\n" ::: "memory");
}
__device__ __forceinline__ void cp_async_wait_all() {
    asm volatile("cp.async.wait_group 0;\n" ::: "memory");
}

// ---- lane bits ---------------------------------------------------------------
struct LB { bool b0, b1, b2, b3, b4; };
template <int I>
__device__ __forceinline__ bool getb(const LB& lb) {
    if constexpr (I == 0)      return lb.b0;
    else if constexpr (I == 1) return lb.b1;
    else if constexpr (I == 2) return lb.b2;
    else if constexpr (I == 3) return lb.b3;
    else                       return lb.b4;
}

// ---- comparator: 2x IMNMX.U32, min to a --------------------------------------
__device__ __forceinline__ void ce(u32& a, u32& b) {
    const u32 mn = min(a, b);
    b = max(a, b);
    a = mn;
}

// Batcher odd-even sort-8, pruned (v[7] = PAD in every lane): 16 comparators.
#define CE(x, y) ce(v[x], v[y])
__device__ __forceinline__ void batcher8(u32 (&v)[VR]) {
    CE(0,1); CE(2,3); CE(4,5);
    CE(0,2); CE(1,3); CE(4,6);
    CE(1,2); CE(5,6);
    CE(0,4); CE(1,5); CE(2,6);
    CE(2,4); CE(3,5);
    CE(1,2); CE(3,4); CE(5,6);
}
__device__ __forceinline__ void stage_J1(u32 (&v)[VR]) {
    CE(0,1); CE(2,3); CE(4,5); CE(6,7);
}
__device__ __forceinline__ void stage_J2(u32 (&v)[VR]) {
    CE(0,2); CE(1,3); CE(4,6); CE(5,7);
}
__device__ __forceinline__ void stage_J4(u32 (&v)[VR]) {
    CE(0,4); CE(1,5); CE(2,6); CE(3,7);
}
#undef CE

// cross-lane reversal: partner lane^LMASK, partner reg 7-r; keepMin = !laneBit(KB)
template <int LMASK, int KB>
__device__ __forceinline__ void rev_cross(u32 (&v)[VR], const LB& lb) {
    u32 o[VR];
#pragma unroll
    for (int r = 0; r < VR; r++) o[r] = __shfl_xor_sync(FULL, v[7 - r], LMASK);
    const bool keep = !getb<KB>(lb);
#pragma unroll
    for (int r = 0; r < VR; r++)
        v[r] = keep ? min(v[r], o[r]) : max(v[r], o[r]);   // 1 IMNMX(P)
}
// cross-lane halving: partner lane^LJ, same reg
template <int LJ, int KB>
__device__ __forceinline__ void halv_cross(u32 (&v)[VR], const LB& lb) {
    u32 o[VR];
#pragma unroll
    for (int r = 0; r < VR; r++) o[r] = __shfl_xor_sync(FULL, v[r], LJ);
    const bool keep = !getb<KB>(lb);
#pragma unroll
    for (int r = 0; r < VR; r++)
        v[r] = keep ? min(v[r], o[r]) : max(v[r], o[r]);
}

__global__ __launch_bounds__(WPB * 32)
void nerf_integrate_kernel(const float* __restrict__ t,
                           const float* __restrict__ sigma,
                           const float* __restrict__ c,
                           float* __restrict__ out_rgb,
                           float* __restrict__ out_wi,
                           int R) {
    const int warp = threadIdx.x >> 5;
    const int lane = threadIdx.x & 31;
    const int ray  = blockIdx.x * WPB + warp;
    if (ray >= R) return;

    __shared__ u32 sh[WPB][SH_PER_WARP];    // c then sigma
    u32* shw = sh[warp];

    const LB lb = { (lane & 1) != 0, (lane & 2) != 0, (lane & 4) != 0,
                    (lane & 8) != 0, (lane & 16) != 0 };

    const u32*   trow = reinterpret_cast<const u32*>(t) + (size_t)ray * NP1;
    const float* srow = sigma + (size_t)ray * NS;
    const float* crow = c + (size_t)ray * NS * 3;

    // ---- 1. t loads straight into sort slots --------------------------------
    u32 v[VR];
#pragma unroll
    for (int r = 0; r < 6; r++) v[r] = __ldg(trow + r * 32 + lane);
    v[6] = (lane == 0) ? __ldg(trow + 192) : PAD_BITS;
    v[7] = PAD_BITS;

    // ---- 2. prefetch c (144 chunks) + sigma (48 chunks) via cp.async --------
    {
        const u32 shc = (u32)__cvta_generic_to_shared(shw);
        const float4* c4 = reinterpret_cast<const float4*>(crow);
        const float4* s4 = reinterpret_cast<const float4*>(srow);
#pragma unroll
        for (int e = 0; e < 4; e++)
            cp_async16(shc + (e * 32 + lane) * 16, c4 + e * 32 + lane);
        if (lane < 16)
            cp_async16(shc + (128 + lane) * 16, c4 + 128 + lane);
        cp_async16(shc + (SH_S / 4 + lane) * 16, s4 + lane);
        if (lane < 16)
            cp_async16(shc + (SH_S / 4 + 32 + lane) * 16, s4 + 32 + lane);
        cp_async_commit();
    }

    // ---- 3. sort: pruned Batcher-8 per lane, reversal-form bitonic merges ----
    batcher8(v);                                                     // 8-sorted
    rev_cross<1, 0>(v, lb);                                          // m=16
    stage_J4(v); stage_J2(v); stage_J1(v);
    rev_cross<3, 1>(v, lb);                                          // m=32
    halv_cross<1, 0>(v, lb);
    stage_J4(v); stage_J2(v); stage_J1(v);
    rev_cross<7, 2>(v, lb);                                          // m=64
    halv_cross<2, 1>(v, lb); halv_cross<1, 0>(v, lb);
    stage_J4(v); stage_J2(v); stage_J1(v);
    rev_cross<15, 3>(v, lb);                                         // m=128
    halv_cross<4, 2>(v, lb); halv_cross<2, 1>(v, lb); halv_cross<1, 0>(v, lb);
    stage_J4(v); stage_J2(v); stage_J1(v);
    rev_cross<31, 4>(v, lb);                                         // m=256
    halv_cross<8, 3>(v, lb); halv_cross<4, 2>(v, lb);
    halv_cross<2, 1>(v, lb); halv_cross<1, 0>(v, lb);
    stage_J4(v); stage_J2(v); stage_J1(v);
    // sorted: slot i = 8*lane + r ascending; slots 193..255 = 1e30

    // ---- 4. wait prefetch (landed during sort), to float, sdt prefix ---------
    cp_async_wait_all();
    __syncwarp();

    float f[VR];
#pragma unroll
    for (int e = 0; e < VR; e++) f[e] = __uint_as_float(v[e]);

    const float tnext = __uint_as_float(__shfl_down_sync(FULL, v[0], 1));
    const bool active = (lane < 24);

    float pfx[VR];
    {
        float4 s0 = make_float4(0.f,0.f,0.f,0.f), s1 = s0;
        if (active) {
            const float4* sp = reinterpret_cast<const float4*>(
                reinterpret_cast<const float*>(shw + SH_S) + lane * VR);
            s0 = sp[0]; s1 = sp[1];
        }
        const float sarr[VR] = {s0.x,s0.y,s0.z,s0.w,s1.x,s1.y,s1.z,s1.w};
        float run = 0.f;
#pragma unroll
        for (int e = 0; e < VR; e++) {
            float tn = (e < VR - 1) ? f[e + 1] : tnext;
            run += sarr[e] * (tn - f[e]);   // pad lanes: 0 * finite = 0
            pfx[e] = run;
        }
    }

    // ---- 5. warp exclusive scan ------------------------------------------------
    const float tot = pfx[VR - 1];
    float inc = tot;
#pragma unroll
    for (int d = 1; d < 32; d <<= 1) {
        float y = __shfl_up_sync(FULL, inc, d);
        if (lane >= d) inc += y;
    }
    const float excl = inc - tot;

    // ---- 6. weights ---------------------------------------------------------------
    float w[VR];
    {
        float prevE = __expf(-excl);
#pragma unroll
        for (int e = 0; e < VR; e++) {
            float E = __expf(-(excl + pfx[e]));
            w[e] = prevE - E;
            prevE = E;
        }
    }

    // ---- 7. wi out: direct STG.128 (blocked) ----------------------------------------
    if (active) {
        float4* wp = reinterpret_cast<float4*>(out_wi + (size_t)ray * NS + lane * VR);
        wp[0] = make_float4(w[0], w[1], w[2], w[3]);
        wp[1] = make_float4(w[4], w[5], w[6], w[7]);
    }

    // ---- 8. rgb from shared c, compile-time channels ----------------------------------
    float a0 = 0.f, a1 = 0.f, a2 = 0.f;
    if (active) {
        const float* cl = reinterpret_cast<const float*>(shw) + lane * 24;
#pragma unroll
        for (int q = 0; q < 6; q++) {
            float4 cv = *reinterpret_cast<const float4*>(cl + 4 * q);
            const float cj[4] = {cv.x, cv.y, cv.z, cv.w};
#pragma unroll
            for (int j = 0; j < 4; j++) {
                const int k  = 4 * q + j;
                const int e  = k / 3;
                const int ch = k - 3 * e;
                const float p = w[e] * cj[j];
                if (ch == 0)      a0 += p;
                else if (ch == 1) a1 += p;
                else              a2 += p;
            }
        }
    }

    // ---- 9. reduce rgb, write ---------------------------------------------------------
#pragma unroll
    for (int d = 16; d > 0; d >>= 1) {
        a0 += __shfl_xor_sync(FULL, a0, d);
        a1 += __shfl_xor_sync(FULL, a1, d);
        a2 += __shfl_xor_sync(FULL, a2, d);
    }
    if (lane < 3) {
        const float val = (lane == 0) ? a0 : ((lane == 1) ? a1 : a2);
        out_rgb[(size_t)ray * 3 + lane] = val;
    }
}

extern "C" void kernel_launch(void* const* d_in, const int* in_sizes, int n_in,
                              void* d_out, int out_size) {
    const float* t     = (const float*)d_in[0];
    const float* sigma = (const float*)d_in[1];
    const float* c     = (const float*)d_in[2];

    const int R = in_sizes[0] / NP1;

    float* out_rgb = (float*)d_out;
    float* out_wi  = out_rgb + (size_t)R * 3;

    const int blocks = (R + WPB - 1) / WPB;
    nerf_integrate_kernel<<<blocks, WPB * 32>>>(t, sigma, c, out_rgb, out_wi, R);
}